// round 15
// baseline (speedup 1.0000x reference)
#include <cuda_runtime.h>
#include <math.h>

// ---------------- problem constants ----------------
#define QO    16
#define QI    16
#define NC0   8          // scalar channels
#define NC1   4          // vector channels
#define NG    8          // gaussians
#define KTAP  125        // 5^3
#define DIMC  20         // C0 + 3*C1
#define NCH   320        // DIMC * 16
#define PP    8
#define PPAD  12
#define VOX   512        // 8^3
#define WROW  40000      // NCH * KTAP  (per out-channel row length)
#define SPLIT 8
#define ICB   4

// ---------------- device scratch (static: no allocs allowed) ----------------
__device__ float g_W[(size_t)NCH * NCH * KTAP];          // 51.2 MB  [o][i][tap]
__device__ float g_xp[(size_t)NCH * PPAD * PPAD * PPAD]; // 2.2 MB   [ch][12][12][12]
__device__ float g_partial[(size_t)SPLIT * NCH * VOX];   // 5.2 MB

// ============================================================================
// Kernel A: build W[o][i][tap].  One block per (p,q); lane = tap k (coalesced
// stores along the innermost tap axis).
// ============================================================================
__global__ void __launch_bounds__(128) build_W_kernel(
    const float* __restrict__ q_in, const float* __restrict__ q_out,
    const float* __restrict__ w_ss, const float* __restrict__ w_vs,
    const float* __restrict__ w_sv, const float* __restrict__ w_vv0,
    const float* __restrict__ w_vv1)
{
    __shared__ float s[1280];
    int t = threadIdx.x;
    for (int i = t; i < 1280; i += 128) {
        float v;
        if      (i < 512)  v = w_ss[i];
        else if (i < 768)  v = w_vs[i - 512];
        else if (i < 1024) v = w_sv[i - 768];
        else if (i < 1152) v = w_vv0[i - 1024];
        else               v = w_vv1[i - 1152];
        s[i] = v;
    }
    __syncthreads();
    if (t >= KTAP) return;

    const float* sss = s;
    const float* svs = s + 512;
    const float* ssv = s + 768;
    const float* sv0 = s + 1024;
    const float* sv1 = s + 1152;

    int p = blockIdx.x >> 4;
    int q = blockIdx.x & 15;
    int k = t;
    int kz = k / 25, ky = (k / 5) % 5, kx = k % 5;

    // v = p_off - (q_out - q_in), components in (z,y,x) stacking order
    float v0 = (float)(kz - 2) - (q_out[p * 3 + 0] - q_in[q * 3 + 0]);
    float v1 = (float)(ky - 2) - (q_out[p * 3 + 1] - q_in[q * 3 + 1]);
    float v2 = (float)(kx - 2) - (q_out[p * 3 + 2] - q_in[q * 3 + 2]);
    float r = sqrtf(v0 * v0 + v1 * v1 + v2 * v2);
    float u0 = 0.f, u1 = 0.f, u2 = 0.f;
    if (r > 1e-6f) { float inv = 1.0f / r; u0 = v0 * inv; u1 = v1 * inv; u2 = v2 * inv; }

    // gaussian RBF: centers linspace(0, 5.5, 8), sigma = 5.5/7
    const float step = 5.5f / 7.0f;
    const float invs = 7.0f / 5.5f;
    float R[NG];
#pragma unroll
    for (int g = 0; g < NG; g++) {
        float d = (r - step * (float)g) * invs;
        R[g] = expf(-0.5f * d * d);
    }

    // --- (0,0,0) scalar->scalar ---
#pragma unroll
    for (int a = 0; a < NC0; a++)
#pragma unroll
        for (int c = 0; c < NC0; c++) {
            float S = 0.f;
#pragma unroll
            for (int g = 0; g < NG; g++) S = fmaf(sss[(a * 8 + c) * 8 + g], R[g], S);
            g_W[(size_t)(a * 16 + p) * WROW + (c * 16 + q) * KTAP + k] = S;
        }
    // --- (1,0,1) vector-in -> scalar-out : row a, col 8 + c*3 + m ---
#pragma unroll
    for (int a = 0; a < NC0; a++)
#pragma unroll
        for (int c = 0; c < NC1; c++) {
            float S = 0.f;
#pragma unroll
            for (int g = 0; g < NG; g++) S = fmaf(ssv[(a * 4 + c) * 8 + g], R[g], S);
            size_t ob = (size_t)(a * 16 + p) * WROW;
            g_W[ob + ((8 + c * 3 + 0) * 16 + q) * KTAP + k] = S * u0;
            g_W[ob + ((8 + c * 3 + 1) * 16 + q) * KTAP + k] = S * u1;
            g_W[ob + ((8 + c * 3 + 2) * 16 + q) * KTAP + k] = S * u2;
        }
    // --- (0,1,1) scalar-in -> vector-out : row 8 + a*3 + m, col c ---
#pragma unroll
    for (int a = 0; a < NC1; a++)
#pragma unroll
        for (int c = 0; c < NC0; c++) {
            float S = 0.f;
#pragma unroll
            for (int g = 0; g < NG; g++) S = fmaf(svs[(a * 8 + c) * 8 + g], R[g], S);
            int ii = (c * 16 + q) * KTAP + k;
            g_W[(size_t)((8 + a * 3 + 0) * 16 + p) * WROW + ii] = S * u0;
            g_W[(size_t)((8 + a * 3 + 1) * 16 + p) * WROW + ii] = S * u1;
            g_W[(size_t)((8 + a * 3 + 2) * 16 + p) * WROW + ii] = S * u2;
        }
    // --- vector->vector : identity (vv0) + skew cross-product (vv1) ---
    const float c707 = 0.7071067811865476f;
#pragma unroll
    for (int a = 0; a < NC1; a++)
#pragma unroll
        for (int c = 0; c < NC1; c++) {
            float S0 = 0.f, S1 = 0.f;
#pragma unroll
            for (int g = 0; g < NG; g++) {
                S0 = fmaf(sv0[(a * 4 + c) * 8 + g], R[g], S0);
                S1 = fmaf(sv1[(a * 4 + c) * 8 + g], R[g], S1);
            }
            S1 *= c707;
            // M[i][j] = sum_m eps[i][m][j] * u[m]  (skew matrix of u)
            float M00 = S0,        M01 = -S1 * u2,  M02 =  S1 * u1;
            float M10 = S1 * u2,   M11 = S0,        M12 = -S1 * u0;
            float M20 = -S1 * u1,  M21 = S1 * u0,   M22 = S0;
            float M[3][3] = {{M00, M01, M02}, {M10, M11, M12}, {M20, M21, M22}};
#pragma unroll
            for (int i = 0; i < 3; i++)
#pragma unroll
                for (int j = 0; j < 3; j++)
                    g_W[(size_t)((8 + a * 3 + i) * 16 + p) * WROW +
                        ((8 + c * 3 + j) * 16 + q) * KTAP + k] = M[i][j];
        }
}

// ============================================================================
// Kernel B: zero-pad x (1,20,16,8,8,8) -> g_xp [320][12][12][12]
// ============================================================================
__global__ void __launch_bounds__(256) pad_x_kernel(const float* __restrict__ x)
{
    int idx = blockIdx.x * 256 + threadIdx.x;
    if (idx >= NCH * 1728) return;
    int ch = idx / 1728;
    int r  = idx - ch * 1728;
    int z = r / 144, y = (r / 12) % 12, xx = r % 12;
    float v = 0.f;
    if (z >= 2 && z < 10 && y >= 2 && y < 10 && xx >= 2 && xx < 10)
        v = x[ch * 512 + (z - 2) * 64 + (y - 2) * 8 + (xx - 2)];
    g_xp[idx] = v;
}

// ============================================================================
// Kernel C: split-K dense conv.  grid = (20 outch-tiles, 2 z-slabs, 8 splits).
// Block: 256 threads = 8 outch-pairs x 32 (z,y) rows. Thread: 2 outch x 8 x.
// smem: W chunk [16][ICB][125] + x slab [ICB][8 planes][12][12] = 50.4 KB.
// Inner loop per (ic,dz,dy): 3 conflict-free LDS.128 + 2 broadcast w loads
// + 80 FFMA  ->  FFMA-pipe bound.
// ============================================================================
__global__ void __launch_bounds__(256) conv_kernel()
{
    extern __shared__ float smem[];
    float* sW = smem;              // 16*ICB*125 = 8000 floats
    float* sX = smem + 16 * ICB * 125; // ICB*8*144 = 4608 floats

    int octile = blockIdx.x;
    int slab   = blockIdx.y;
    int split  = blockIdx.z;
    int tid = threadIdx.x;
    int ocp = tid >> 5;        // 0..7 : out-channel pair
    int row = tid & 31;        // 0..31 : (zz,y)
    int zz  = row >> 3;        // 0..3
    int y   = row & 7;         // 0..7
    int zs  = slab * 4;

    float acc0[8], acc1[8];
#pragma unroll
    for (int j = 0; j < 8; j++) { acc0[j] = 0.f; acc1[j] = 0.f; }

    for (int icb = 0; icb < 40; icb += ICB) {
        int icbase = split * 40 + icb;
        __syncthreads();
        // stage W chunk: 16 out-ch x ICB in-ch x 125 taps (contiguous runs)
        for (int idx = tid; idx < 16 * ICB * KTAP; idx += 256) {
            int oo = idx / (ICB * KTAP);
            int r  = idx - oo * (ICB * KTAP);
            sW[idx] = g_W[(size_t)(octile * 16 + oo) * WROW + icbase * KTAP + r];
        }
        // stage x slab: ICB channels x 8 z-planes x 144 (contiguous runs)
        for (int idx = tid; idx < ICB * 1152; idx += 256) {
            int ic = idx / 1152;
            int r  = idx - ic * 1152;
            sX[idx] = g_xp[(size_t)(icbase + ic) * 1728 + zs * 144 + r];
        }
        __syncthreads();

#pragma unroll 1
        for (int ic = 0; ic < ICB; ic++) {
            const float* wp0 = &sW[(ocp * 2) * (ICB * KTAP) + ic * KTAP];
            const float* wp1 = wp0 + ICB * KTAP;
            const float* xb  = &sX[ic * 1152 + zz * 144 + y * 12];
#pragma unroll 1
            for (int dz = 0; dz < 5; dz++) {
                const float* xpl = xb + dz * 144;
                const float* w0r = wp0 + dz * 25;
                const float* w1r = wp1 + dz * 25;
#pragma unroll
                for (int dy = 0; dy < 5; dy++) {
                    float4 A = *(const float4*)(xpl + dy * 12);
                    float4 B = *(const float4*)(xpl + dy * 12 + 4);
                    float4 C = *(const float4*)(xpl + dy * 12 + 8);
                    float xr[12] = {A.x, A.y, A.z, A.w,
                                    B.x, B.y, B.z, B.w,
                                    C.x, C.y, C.z, C.w};
#pragma unroll
                    for (int dx = 0; dx < 5; dx++) {
                        float w0 = w0r[dy * 5 + dx];
                        float w1 = w1r[dy * 5 + dx];
#pragma unroll
                        for (int j = 0; j < 8; j++) {
                            acc0[j] = fmaf(w0, xr[dx + j], acc0[j]);
                            acc1[j] = fmaf(w1, xr[dx + j], acc1[j]);
                        }
                    }
                }
            }
        }
    }

    int o0 = octile * 16 + ocp * 2;
    int z  = zs + zz;
    size_t base = (size_t)split * NCH * VOX + z * 64 + y * 8;
    float4* p0 = (float4*)&g_partial[base + (size_t)o0 * 512];
    p0[0] = make_float4(acc0[0], acc0[1], acc0[2], acc0[3]);
    p0[1] = make_float4(acc0[4], acc0[5], acc0[6], acc0[7]);
    float4* p1 = (float4*)&g_partial[base + (size_t)(o0 + 1) * 512];
    p1[0] = make_float4(acc1[0], acc1[1], acc1[2], acc1[3]);
    p1[1] = make_float4(acc1[4], acc1[5], acc1[6], acc1[7]);
}

// ============================================================================
// Kernel D: reduce split-K partials + bias
// ============================================================================
__global__ void __launch_bounds__(256) reduce_kernel(
    const float* __restrict__ bias, float* __restrict__ out)
{
    int idx = blockIdx.x * 256 + threadIdx.x;
    if (idx >= NCH * VOX) return;
    float s = 0.f;
#pragma unroll
    for (int sp = 0; sp < SPLIT; sp++)
        s += g_partial[(size_t)sp * NCH * VOX + idx];
    int o  = idx >> 9;    // out channel 0..319
    int ao = o >> 4;      // dim_out index 0..19
    if (ao < NC0) s += bias[ao];
    out[idx] = s;
}

// ============================================================================
extern "C" void kernel_launch(void* const* d_in, const int* in_sizes, int n_in,
                              void* d_out, int out_size)
{
    const float* x     = (const float*)d_in[0];
    const float* q_in  = (const float*)d_in[1];
    const float* q_out = (const float*)d_in[2];
    const float* w_ss  = (const float*)d_in[3];
    const float* w_vs  = (const float*)d_in[4];
    const float* w_sv  = (const float*)d_in[5];
    const float* w_vv0 = (const float*)d_in[6];
    const float* w_vv1 = (const float*)d_in[7];
    const float* bias  = (const float*)d_in[8];
    float* out = (float*)d_out;

    (void)in_sizes; (void)n_in; (void)out_size;

    const int conv_smem = (16 * ICB * 125 + ICB * 8 * 144) * (int)sizeof(float); // 50432 B
    cudaFuncSetAttribute(conv_kernel, cudaFuncAttributeMaxDynamicSharedMemorySize, conv_smem);

    build_W_kernel<<<QO * QI, 128>>>(q_in, q_out, w_ss, w_vs, w_sv, w_vv0, w_vv1);
    pad_x_kernel<<<(NCH * 1728 + 255) / 256, 256>>>(x);
    dim3 grid(20, 2, SPLIT);
    conv_kernel<<<grid, 256, conv_smem>>>();
    reduce_kernel<<<(NCH * VOX + 255) / 256, 256>>>(bias, out);
}

// round 16
// speedup vs baseline: 1.0042x; 1.0042x over previous
#include <cuda_runtime.h>
#include <math.h>

// ---------------- problem constants ----------------
#define QO    16
#define QI    16
#define NC0   8          // scalar channels
#define NC1   4          // vector channels
#define NG    8          // gaussians
#define KTAP  125        // 5^3
#define DIMC  20         // C0 + 3*C1
#define NCH   320        // DIMC * 16
#define PP    8
#define PPAD  12
#define VOX   512        // 8^3
#define WROW  40000      // NCH * KTAP  (per out-channel row length)
#define SPLIT 8
#define ICB   4

// ---------------- device scratch (static: no allocs allowed) ----------------
__device__ float g_W[(size_t)NCH * NCH * KTAP];          // 51.2 MB  [o][i][tap]
__device__ float g_xp[(size_t)NCH * PPAD * PPAD * PPAD]; // 2.2 MB   [ch][12][12][12]
__device__ float g_partial[(size_t)SPLIT * NCH * VOX];   // 5.2 MB

// ============================================================================
// Kernel A: build W[o][i][tap].  One block per (p,q); lane = tap k (coalesced
// stores along the innermost tap axis).
// ============================================================================
__global__ void __launch_bounds__(128) build_W_kernel(
    const float* __restrict__ q_in, const float* __restrict__ q_out,
    const float* __restrict__ w_ss, const float* __restrict__ w_vs,
    const float* __restrict__ w_sv, const float* __restrict__ w_vv0,
    const float* __restrict__ w_vv1)
{
    __shared__ float s[1280];
    int t = threadIdx.x;
    for (int i = t; i < 1280; i += 128) {
        float v;
        if      (i < 512)  v = w_ss[i];
        else if (i < 768)  v = w_vs[i - 512];
        else if (i < 1024) v = w_sv[i - 768];
        else if (i < 1152) v = w_vv0[i - 1024];
        else               v = w_vv1[i - 1152];
        s[i] = v;
    }
    __syncthreads();
    if (t >= KTAP) return;

    const float* sss = s;
    const float* svs = s + 512;
    const float* ssv = s + 768;
    const float* sv0 = s + 1024;
    const float* sv1 = s + 1152;

    int p = blockIdx.x >> 4;
    int q = blockIdx.x & 15;
    int k = t;
    int kz = k / 25, ky = (k / 5) % 5, kx = k % 5;

    // v = p_off - (q_out - q_in), components in (z,y,x) stacking order
    float v0 = (float)(kz - 2) - (q_out[p * 3 + 0] - q_in[q * 3 + 0]);
    float v1 = (float)(ky - 2) - (q_out[p * 3 + 1] - q_in[q * 3 + 1]);
    float v2 = (float)(kx - 2) - (q_out[p * 3 + 2] - q_in[q * 3 + 2]);
    float r = sqrtf(v0 * v0 + v1 * v1 + v2 * v2);
    float u0 = 0.f, u1 = 0.f, u2 = 0.f;
    if (r > 1e-6f) { float inv = 1.0f / r; u0 = v0 * inv; u1 = v1 * inv; u2 = v2 * inv; }

    // gaussian RBF: centers linspace(0, 5.5, 8), sigma = 5.5/7
    const float step = 5.5f / 7.0f;
    const float invs = 7.0f / 5.5f;
    float R[NG];
#pragma unroll
    for (int g = 0; g < NG; g++) {
        float d = (r - step * (float)g) * invs;
        R[g] = expf(-0.5f * d * d);
    }

    // --- (0,0,0) scalar->scalar ---
#pragma unroll
    for (int a = 0; a < NC0; a++)
#pragma unroll
        for (int c = 0; c < NC0; c++) {
            float S = 0.f;
#pragma unroll
            for (int g = 0; g < NG; g++) S = fmaf(sss[(a * 8 + c) * 8 + g], R[g], S);
            g_W[(size_t)(a * 16 + p) * WROW + (c * 16 + q) * KTAP + k] = S;
        }
    // --- (1,0,1) vector-in -> scalar-out : row a, col 8 + c*3 + m ---
#pragma unroll
    for (int a = 0; a < NC0; a++)
#pragma unroll
        for (int c = 0; c < NC1; c++) {
            float S = 0.f;
#pragma unroll
            for (int g = 0; g < NG; g++) S = fmaf(ssv[(a * 4 + c) * 8 + g], R[g], S);
            size_t ob = (size_t)(a * 16 + p) * WROW;
            g_W[ob + ((8 + c * 3 + 0) * 16 + q) * KTAP + k] = S * u0;
            g_W[ob + ((8 + c * 3 + 1) * 16 + q) * KTAP + k] = S * u1;
            g_W[ob + ((8 + c * 3 + 2) * 16 + q) * KTAP + k] = S * u2;
        }
    // --- (0,1,1) scalar-in -> vector-out : row 8 + a*3 + m, col c ---
#pragma unroll
    for (int a = 0; a < NC1; a++)
#pragma unroll
        for (int c = 0; c < NC0; c++) {
            float S = 0.f;
#pragma unroll
            for (int g = 0; g < NG; g++) S = fmaf(svs[(a * 8 + c) * 8 + g], R[g], S);
            int ii = (c * 16 + q) * KTAP + k;
            g_W[(size_t)((8 + a * 3 + 0) * 16 + p) * WROW + ii] = S * u0;
            g_W[(size_t)((8 + a * 3 + 1) * 16 + p) * WROW + ii] = S * u1;
            g_W[(size_t)((8 + a * 3 + 2) * 16 + p) * WROW + ii] = S * u2;
        }
    // --- vector->vector : identity (vv0) + skew cross-product (vv1) ---
    const float c707 = 0.7071067811865476f;
#pragma unroll
    for (int a = 0; a < NC1; a++)
#pragma unroll
        for (int c = 0; c < NC1; c++) {
            float S0 = 0.f, S1 = 0.f;
#pragma unroll
            for (int g = 0; g < NG; g++) {
                S0 = fmaf(sv0[(a * 4 + c) * 8 + g], R[g], S0);
                S1 = fmaf(sv1[(a * 4 + c) * 8 + g], R[g], S1);
            }
            S1 *= c707;
            // M[i][j] = sum_m eps[i][m][j] * u[m]  (skew matrix of u)
            float M00 = S0,        M01 = -S1 * u2,  M02 =  S1 * u1;
            float M10 = S1 * u2,   M11 = S0,        M12 = -S1 * u0;
            float M20 = -S1 * u1,  M21 = S1 * u0,   M22 = S0;
            float M[3][3] = {{M00, M01, M02}, {M10, M11, M12}, {M20, M21, M22}};
#pragma unroll
            for (int i = 0; i < 3; i++)
#pragma unroll
                for (int j = 0; j < 3; j++)
                    g_W[(size_t)((8 + a * 3 + i) * 16 + p) * WROW +
                        ((8 + c * 3 + j) * 16 + q) * KTAP + k] = M[i][j];
        }
}

// ============================================================================
// Kernel B: zero-pad x (1,20,16,8,8,8) -> g_xp [320][12][12][12]
// ============================================================================
__global__ void __launch_bounds__(256) pad_x_kernel(const float* __restrict__ x)
{
    int idx = blockIdx.x * 256 + threadIdx.x;
    if (idx >= NCH * 1728) return;
    int ch = idx / 1728;
    int r  = idx - ch * 1728;
    int z = r / 144, y = (r / 12) % 12, xx = r % 12;
    float v = 0.f;
    if (z >= 2 && z < 10 && y >= 2 && y < 10 && xx >= 2 && xx < 10)
        v = x[ch * 512 + (z - 2) * 64 + (y - 2) * 8 + (xx - 2)];
    g_xp[idx] = v;
}

// ============================================================================
// Kernel C: split-K dense conv.  grid = (20 outch-tiles, 2 z-slabs, 8 splits).
// Block: 256 threads = 8 outch-pairs x 32 (z,y) rows. Thread: 2 outch x 8 x.
// smem: W chunk [16][ICB][125] + x slab [ICB][8 planes][12][12] = 50.4 KB.
// Inner loop per (ic,dz,dy): 3 conflict-free LDS.128 + 2 broadcast w loads
// + 80 FFMA  ->  FFMA-pipe bound.
// ============================================================================
__global__ void __launch_bounds__(256) conv_kernel()
{
    extern __shared__ float smem[];
    float* sW = smem;              // 16*ICB*125 = 8000 floats
    float* sX = smem + 16 * ICB * 125; // ICB*8*144 = 4608 floats

    int octile = blockIdx.x;
    int slab   = blockIdx.y;
    int split  = blockIdx.z;
    int tid = threadIdx.x;
    int ocp = tid >> 5;        // 0..7 : out-channel pair
    int row = tid & 31;        // 0..31 : (zz,y)
    int zz  = row >> 3;        // 0..3
    int y   = row & 7;         // 0..7
    int zs  = slab * 4;

    float acc0[8], acc1[8];
#pragma unroll
    for (int j = 0; j < 8; j++) { acc0[j] = 0.f; acc1[j] = 0.f; }

    for (int icb = 0; icb < 40; icb += ICB) {
        int icbase = split * 40 + icb;
        __syncthreads();
        // stage W chunk: 16 out-ch x ICB in-ch x 125 taps (contiguous runs)
        for (int idx = tid; idx < 16 * ICB * KTAP; idx += 256) {
            int oo = idx / (ICB * KTAP);
            int r  = idx - oo * (ICB * KTAP);
            sW[idx] = g_W[(size_t)(octile * 16 + oo) * WROW + icbase * KTAP + r];
        }
        // stage x slab: ICB channels x 8 z-planes x 144 (contiguous runs)
        for (int idx = tid; idx < ICB * 1152; idx += 256) {
            int ic = idx / 1152;
            int r  = idx - ic * 1152;
            sX[idx] = g_xp[(size_t)(icbase + ic) * 1728 + zs * 144 + r];
        }
        __syncthreads();

#pragma unroll 1
        for (int ic = 0; ic < ICB; ic++) {
            const float* wp0 = &sW[(ocp * 2) * (ICB * KTAP) + ic * KTAP];
            const float* wp1 = wp0 + ICB * KTAP;
            const float* xb  = &sX[ic * 1152 + zz * 144 + y * 12];
#pragma unroll 1
            for (int dz = 0; dz < 5; dz++) {
                const float* xpl = xb + dz * 144;
                const float* w0r = wp0 + dz * 25;
                const float* w1r = wp1 + dz * 25;
#pragma unroll
                for (int dy = 0; dy < 5; dy++) {
                    float4 A = *(const float4*)(xpl + dy * 12);
                    float4 B = *(const float4*)(xpl + dy * 12 + 4);
                    float4 C = *(const float4*)(xpl + dy * 12 + 8);
                    float xr[12] = {A.x, A.y, A.z, A.w,
                                    B.x, B.y, B.z, B.w,
                                    C.x, C.y, C.z, C.w};
#pragma unroll
                    for (int dx = 0; dx < 5; dx++) {
                        float w0 = w0r[dy * 5 + dx];
                        float w1 = w1r[dy * 5 + dx];
#pragma unroll
                        for (int j = 0; j < 8; j++) {
                            acc0[j] = fmaf(w0, xr[dx + j], acc0[j]);
                            acc1[j] = fmaf(w1, xr[dx + j], acc1[j]);
                        }
                    }
                }
            }
        }
    }

    int o0 = octile * 16 + ocp * 2;
    int z  = zs + zz;
    size_t base = (size_t)split * NCH * VOX + z * 64 + y * 8;
    float4* p0 = (float4*)&g_partial[base + (size_t)o0 * 512];
    p0[0] = make_float4(acc0[0], acc0[1], acc0[2], acc0[3]);
    p0[1] = make_float4(acc0[4], acc0[5], acc0[6], acc0[7]);
    float4* p1 = (float4*)&g_partial[base + (size_t)(o0 + 1) * 512];
    p1[0] = make_float4(acc1[0], acc1[1], acc1[2], acc1[3]);
    p1[1] = make_float4(acc1[4], acc1[5], acc1[6], acc1[7]);
}

// ============================================================================
// Kernel D: reduce split-K partials + bias
// ============================================================================
__global__ void __launch_bounds__(256) reduce_kernel(
    const float* __restrict__ bias, float* __restrict__ out)
{
    int idx = blockIdx.x * 256 + threadIdx.x;
    if (idx >= NCH * VOX) return;
    float s = 0.f;
#pragma unroll
    for (int sp = 0; sp < SPLIT; sp++)
        s += g_partial[(size_t)sp * NCH * VOX + idx];
    int o  = idx >> 9;    // out channel 0..319
    int ao = o >> 4;      // dim_out index 0..19
    if (ao < NC0) s += bias[ao];
    out[idx] = s;
}

// ============================================================================
extern "C" void kernel_launch(void* const* d_in, const int* in_sizes, int n_in,
                              void* d_out, int out_size)
{
    const float* x     = (const float*)d_in[0];
    const float* q_in  = (const float*)d_in[1];
    const float* q_out = (const float*)d_in[2];
    const float* w_ss  = (const float*)d_in[3];
    const float* w_vs  = (const float*)d_in[4];
    const float* w_sv  = (const float*)d_in[5];
    const float* w_vv0 = (const float*)d_in[6];
    const float* w_vv1 = (const float*)d_in[7];
    const float* bias  = (const float*)d_in[8];
    float* out = (float*)d_out;

    (void)in_sizes; (void)n_in; (void)out_size;

    const int conv_smem = (16 * ICB * 125 + ICB * 8 * 144) * (int)sizeof(float); // 50432 B
    cudaFuncSetAttribute(conv_kernel, cudaFuncAttributeMaxDynamicSharedMemorySize, conv_smem);

    build_W_kernel<<<QO * QI, 128>>>(q_in, q_out, w_ss, w_vs, w_sv, w_vv0, w_vv1);
    pad_x_kernel<<<(NCH * 1728 + 255) / 256, 256>>>(x);
    dim3 grid(20, 2, SPLIT);
    conv_kernel<<<grid, 256, conv_smem>>>();
    reduce_kernel<<<(NCH * VOX + 255) / 256, 256>>>(bias, out);
}